// round 10
// baseline (speedup 1.0000x reference)
#include <cuda_runtime.h>
#include <cuda_bf16.h>
#include <cstdint>

#define NND 50000
#define NE  800000
#define HID 128

#define SCB 256
#define NSB ((NND + SCB - 1) / SCB)
#define CHUNK 16

#define PADB 272           // bytes per smem tile row (128 bf16 + 8 pad)
#define TILEB (128 * PADB)

#define SM_AHI 0
#define SM_ALO (SM_AHI + TILEB)
#define SM_WHI (SM_ALO + TILEB)
#define SM_WLO (SM_WHI + TILEB)
#define SM_FC  (SM_WLO + TILEB)
#define SM_TOTAL (SM_FC + 128 * 4 * 4)

// ---------------- device scratch ----------------
__device__ int   g_deg[NND];
__device__ int   g_rowptr[NND + 1];
__device__ int   g_cursor[NND];
__device__ int   g_col[NE];
__device__ int   g_part[NSB];
__device__ int   g_partoff[NSB];
__device__ float g_bufA[(size_t)NND * HID];
__device__ float g_bufB[(size_t)NND * HID];
__device__ __nv_bfloat16 g_wb[8][16384];  // {W1a,W1b,W2a,W2b} x {hi,lo}, [n][k]
__device__ int   g_is64;
__device__ unsigned g_ctr[2];             // work-stealing counters (per gather pass)

// ---------------- PTX helpers ----------------
__device__ __forceinline__ uint32_t smem_u32(const void* p) {
    uint32_t a;
    asm("{ .reg .u64 t; cvta.to.shared.u64 t, %1; cvt.u32.u64 %0, t; }" : "=r"(a) : "l"(p));
    return a;
}
__device__ __forceinline__ void ldsm_x4(uint32_t* r, uint32_t addr) {
    asm volatile("ldmatrix.sync.aligned.m8n8.x4.shared.b16 {%0,%1,%2,%3}, [%4];"
                 : "=r"(r[0]), "=r"(r[1]), "=r"(r[2]), "=r"(r[3]) : "r"(addr));
}
__device__ __forceinline__ void ldsm_x2(uint32_t* r, uint32_t addr) {
    asm volatile("ldmatrix.sync.aligned.m8n8.x2.shared.b16 {%0,%1}, [%2];"
                 : "=r"(r[0]), "=r"(r[1]) : "r"(addr));
}
__device__ __forceinline__ void mma16816(float* c, const uint32_t* a, const uint32_t* b) {
    asm volatile("mma.sync.aligned.m16n8k16.row.col.f32.bf16.bf16.f32 "
                 "{%0,%1,%2,%3}, {%4,%5,%6,%7}, {%8,%9}, {%0,%1,%2,%3};"
                 : "+f"(c[0]), "+f"(c[1]), "+f"(c[2]), "+f"(c[3])
                 : "r"(a[0]), "r"(a[1]), "r"(a[2]), "r"(a[3]), "r"(b[0]), "r"(b[1]));
}
__device__ __forceinline__ uint32_t pack_bf16_hi(float v0, float v1, uint32_t& lop) {
    __nv_bfloat16 h0 = __float2bfloat16(v0);
    __nv_bfloat16 h1 = __float2bfloat16(v1);
    __nv_bfloat16 l0 = __float2bfloat16(v0 - __bfloat162float(h0));
    __nv_bfloat16 l1 = __float2bfloat16(v1 - __bfloat162float(h1));
    lop = ((uint32_t)__bfloat16_as_ushort(l1) << 16) | __bfloat16_as_ushort(l0);
    return ((uint32_t)__bfloat16_as_ushort(h1) << 16) | __bfloat16_as_ushort(h0);
}

// ---------------- edge dtype detection ----------------
__global__ void k_detect(const long long* __restrict__ ei) {
    int lane = threadIdx.x & 31;
    unsigned long long h = ((unsigned long long)ei[lane]) >> 32;
    h |= ((unsigned long long)ei[lane + 32]) >> 32;
    unsigned any = __ballot_sync(0xffffffffu, h != 0ull);
    if (lane == 0) g_is64 = (any == 0u) ? 1 : 0;
}

// ---------------- CSR build (separate kernels, proven) ----------------
__global__ void k_zero_deg() {
    int i = blockIdx.x * blockDim.x + threadIdx.x;
    if (i < NND) g_deg[i] = 0;
    if (i < 2) g_ctr[i] = 0;
}
__global__ void k_hist(const void* __restrict__ ei) {
    int e = blockIdx.x * blockDim.x + threadIdx.x;
    if (e >= NE) return;
    int d;
    if (g_is64) d = (int)reinterpret_cast<const long long*>(ei)[NE + e];
    else        d = reinterpret_cast<const int*>(ei)[NE + e];
    atomicAdd(&g_deg[d], 1);
}
__global__ void k_s1() {
    int b = blockIdx.x, t = threadIdx.x;
    int idx = b * SCB + t;
    int v = (idx < NND) ? g_deg[idx] : 0;
#pragma unroll
    for (int o = 16; o; o >>= 1) v += __shfl_down_sync(0xffffffffu, v, o);
    __shared__ int ws[8];
    if ((t & 31) == 0) ws[t >> 5] = v;
    __syncthreads();
    if (t == 0) {
        int s = 0;
#pragma unroll
        for (int i = 0; i < 8; i++) s += ws[i];
        g_part[b] = s;
    }
}
__global__ void k_s2() {
    int t = threadIdx.x, lane = t & 31, w = t >> 5;
    int v = (t < NSB) ? g_part[t] : 0;
    int iv = v;
#pragma unroll
    for (int o = 1; o < 32; o <<= 1) {
        int u = __shfl_up_sync(0xffffffffu, iv, o);
        if (lane >= o) iv += u;
    }
    __shared__ int ws[8], wso[8];
    if (lane == 31) ws[w] = iv;
    __syncthreads();
    if (t == 0) {
        int run = 0;
#pragma unroll
        for (int i = 0; i < 8; i++) { wso[i] = run; run += ws[i]; }
        g_rowptr[NND] = NE;
    }
    __syncthreads();
    if (t < NSB) g_partoff[t] = wso[w] + iv - v;
}
__global__ void k_s3() {
    int b = blockIdx.x, t = threadIdx.x, lane = t & 31, w = t >> 5;
    int idx = b * SCB + t;
    int v = (idx < NND) ? g_deg[idx] : 0;
    int iv = v;
#pragma unroll
    for (int o = 1; o < 32; o <<= 1) {
        int u = __shfl_up_sync(0xffffffffu, iv, o);
        if (lane >= o) iv += u;
    }
    __shared__ int ws[8], wso[8];
    if (lane == 31) ws[w] = iv;
    __syncthreads();
    if (t == 0) {
        int run = 0;
#pragma unroll
        for (int i = 0; i < 8; i++) { wso[i] = run; run += ws[i]; }
    }
    __syncthreads();
    int excl = g_partoff[b] + wso[w] + iv - v;
    if (idx < NND) { g_rowptr[idx] = excl; g_cursor[idx] = excl; }
}
__global__ void k_fill(const void* __restrict__ ei) {
    int e = blockIdx.x * blockDim.x + threadIdx.x;
    if (e >= NE) return;
    int s, d;
    if (g_is64) {
        s = (int)reinterpret_cast<const long long*>(ei)[e];
        d = (int)reinterpret_cast<const long long*>(ei)[NE + e];
    } else {
        s = reinterpret_cast<const int*>(ei)[e];
        d = reinterpret_cast<const int*>(ei)[NE + e];
    }
    int pos = atomicAdd(&g_cursor[d], 1);
    g_col[pos] = s;
}

// ---------------- weight prep ----------------
__global__ void k_prepw(const float* __restrict__ W0, const float* __restrict__ W1,
                        const float* __restrict__ W2, const float* __restrict__ W3) {
    int mat = blockIdx.x;
    const float* W = (mat == 0) ? W0 : (mat == 1) ? W1 : (mat == 2) ? W2 : W3;
    uint32_t* hiB = reinterpret_cast<uint32_t*>(g_wb[mat * 2]);
    uint32_t* loB = reinterpret_cast<uint32_t*>(g_wb[mat * 2 + 1]);
    for (int idx = threadIdx.x; idx < 8192; idx += blockDim.x) {
        int kp = idx & 63, n = idx >> 6, k = kp * 2;
        float a0 = W[k * 128 + n];
        float a1 = W[(k + 1) * 128 + n];
        uint32_t lp, hp = pack_bf16_hi(a0, a1, lp);
        hiB[n * 64 + kp] = hp;
        loB[n * 64 + kp] = lp;
    }
}

// ---------------- chunked work-stealing gather ----------------
// out[i] = in[i] + sum_{j in N(i)} in[j]; warp grabs CHUNK nodes per atomic
__global__ void __launch_bounds__(256) k_gather(const float4* __restrict__ in4,
                                                float4* __restrict__ out4, int which) {
    const int lane = threadIdx.x & 31;
    for (;;) {
        unsigned base;
        if (lane == 0) base = atomicAdd(&g_ctr[which], (unsigned)CHUNK);
        base = __shfl_sync(0xffffffffu, base, 0);
        if (base >= NND) return;
        unsigned stop = base + CHUNK;
        if (stop > NND) stop = NND;
        for (unsigned node = base; node < stop; node++) {
            float4 a0 = in4[(size_t)node * 32 + lane];
            float4 a1 = make_float4(0.f, 0.f, 0.f, 0.f);
            int beg = g_rowptr[node], end = g_rowptr[node + 1];
            int k = beg;
            for (; k + 4 <= end; k += 4) {
                int j0 = g_col[k], j1 = g_col[k + 1], j2 = g_col[k + 2], j3 = g_col[k + 3];
                float4 v0 = in4[(size_t)j0 * 32 + lane];
                float4 v1 = in4[(size_t)j1 * 32 + lane];
                float4 v2 = in4[(size_t)j2 * 32 + lane];
                float4 v3 = in4[(size_t)j3 * 32 + lane];
                a0.x += v0.x; a0.y += v0.y; a0.z += v0.z; a0.w += v0.w;
                a1.x += v1.x; a1.y += v1.y; a1.z += v1.z; a1.w += v1.w;
                a0.x += v2.x; a0.y += v2.y; a0.z += v2.z; a0.w += v2.w;
                a1.x += v3.x; a1.y += v3.y; a1.z += v3.z; a1.w += v3.w;
            }
            for (; k < end; k++) {
                int j = g_col[k];
                float4 v = in4[(size_t)j * 32 + lane];
                a0.x += v.x; a0.y += v.y; a0.z += v.z; a0.w += v.w;
            }
            a0.x += a1.x; a0.y += a1.y; a0.z += a1.z; a0.w += a1.w;
            out4[(size_t)node * 32 + lane] = a0;
        }
    }
}

// ---------------- GEMM core: 3-phase bf16 split, acc in fp32 ----------------
__device__ __forceinline__ void do_gemm(uint32_t smb, int wm, int wn, int lane,
                                        float acc[2][8][4]) {
#pragma unroll
    for (int mt = 0; mt < 2; mt++)
#pragma unroll
        for (int nt = 0; nt < 8; nt++)
#pragma unroll
            for (int i = 0; i < 4; i++) acc[mt][nt][i] = 0.f;

    const uint32_t a_bases[3] = { smb + SM_AHI, smb + SM_AHI, smb + SM_ALO };
    const uint32_t w_bases[3] = { smb + SM_WHI, smb + SM_WLO, smb + SM_WHI };

    const int a_row0 = wm * 32 + (lane & 15);
    const int a_cofs = (lane >> 4) * 8;
    const int b_row0 = wn * 64 + (lane & 7);
    const int b_cofs = ((lane >> 3) & 1) * 8;

#pragma unroll
    for (int p = 0; p < 3; p++) {
        const uint32_t Ab = a_bases[p];
        const uint32_t Wb = w_bases[p];
#pragma unroll
        for (int ks = 0; ks < 8; ks++) {
            const int k0 = ks * 16;
            uint32_t afrag[2][4];
#pragma unroll
            for (int mt = 0; mt < 2; mt++)
                ldsm_x4(afrag[mt], Ab + (uint32_t)(a_row0 + mt * 16) * PADB
                                      + (uint32_t)(k0 + a_cofs) * 2);
            uint32_t bfrag[8][2];
#pragma unroll
            for (int nt = 0; nt < 8; nt++)
                ldsm_x2(bfrag[nt], Wb + (uint32_t)(b_row0 + nt * 8) * PADB
                                      + (uint32_t)(k0 + b_cofs) * 2);
#pragma unroll
            for (int mt = 0; mt < 2; mt++)
#pragma unroll
                for (int nt = 0; nt < 8; nt++)
                    mma16816(acc[mt][nt], afrag[mt], bfrag[nt]);
        }
    }
}

// ---------------- MLP kernel: 2 GEMMs + epilogues ----------------
__global__ void __launch_bounds__(256, 1) k_mlp_mma(
    const float* __restrict__ A,
    const __nv_bfloat16* __restrict__ WaHi, const __nv_bfloat16* __restrict__ WaLo,
    const __nv_bfloat16* __restrict__ WbHi, const __nv_bfloat16* __restrict__ WbLo,
    const float* __restrict__ ba, const float* __restrict__ bb,
    float* __restrict__ out, int final_relu,
    const float* __restrict__ Wfc, const float* __restrict__ bfc) {
    extern __shared__ char sm[];
    const uint32_t smb = smem_u32(sm);
    const int tid = threadIdx.x;
    const int wid = tid >> 5;
    const int lane = tid & 31;
    const int wm = wid & 3;
    const int wn = wid >> 2;
    const int m_base = blockIdx.x * 128;

    // ---- load A tile: fp32 -> bf16 hi/lo ----
    {
#pragma unroll
        for (int it = 0; it < 16; it++) {
            int r = wid * 16 + it;
            int m = m_base + r;
            float4 v = make_float4(0.f, 0.f, 0.f, 0.f);
            if (m < NND) v = *reinterpret_cast<const float4*>(A + (size_t)m * 128 + lane * 4);
            uint32_t l0, l1;
            uint32_t h0 = pack_bf16_hi(v.x, v.y, l0);
            uint32_t h1 = pack_bf16_hi(v.z, v.w, l1);
            uint32_t off = (uint32_t)r * PADB + (uint32_t)lane * 8;
            *reinterpret_cast<uint2*>(sm + SM_AHI + off) = make_uint2(h0, h1);
            *reinterpret_cast<uint2*>(sm + SM_ALO + off) = make_uint2(l0, l1);
        }
    }
    // ---- copy Wa blobs ----
    {
        const float4* sh = reinterpret_cast<const float4*>(WaHi);
        const float4* sl = reinterpret_cast<const float4*>(WaLo);
#pragma unroll
        for (int i = 0; i < 8; i++) {
            int idx = i * 256 + tid;
            int row = idx >> 4, c16 = idx & 15;
            uint32_t off = (uint32_t)row * PADB + (uint32_t)c16 * 16;
            *reinterpret_cast<float4*>(sm + SM_WHI + off) = sh[idx];
            *reinterpret_cast<float4*>(sm + SM_WLO + off) = sl[idx];
        }
    }
    __syncthreads();

    float acc[2][8][4];
    do_gemm(smb, wm, wn, lane, acc);
    __syncthreads();

    // ---- epilogue 1: bias + relu -> back into A tile ----
    {
        const int r0 = wm * 32 + (lane >> 2);
#pragma unroll
        for (int mt = 0; mt < 2; mt++) {
#pragma unroll
            for (int nt = 0; nt < 8; nt++) {
                int c = wn * 64 + nt * 8 + (lane & 3) * 2;
                float bc0 = __ldg(ba + c), bc1 = __ldg(ba + c + 1);
                float v0 = acc[mt][nt][0] + bc0;
                float v1 = acc[mt][nt][1] + bc1;
                float v2 = acc[mt][nt][2] + bc0;
                float v3 = acc[mt][nt][3] + bc1;
                v0 = v0 > 0.f ? v0 : 0.f; v1 = v1 > 0.f ? v1 : 0.f;
                v2 = v2 > 0.f ? v2 : 0.f; v3 = v3 > 0.f ? v3 : 0.f;
                int r = r0 + mt * 16;
                uint32_t lo;
                uint32_t hi = pack_bf16_hi(v0, v1, lo);
                uint32_t off = (uint32_t)r * PADB + (uint32_t)c * 2;
                *reinterpret_cast<uint32_t*>(sm + SM_AHI + off) = hi;
                *reinterpret_cast<uint32_t*>(sm + SM_ALO + off) = lo;
                hi = pack_bf16_hi(v2, v3, lo);
                off = (uint32_t)(r + 8) * PADB + (uint32_t)c * 2;
                *reinterpret_cast<uint32_t*>(sm + SM_AHI + off) = hi;
                *reinterpret_cast<uint32_t*>(sm + SM_ALO + off) = lo;
            }
        }
    }
    // ---- copy Wb blobs ----
    {
        const float4* sh = reinterpret_cast<const float4*>(WbHi);
        const float4* sl = reinterpret_cast<const float4*>(WbLo);
#pragma unroll
        for (int i = 0; i < 8; i++) {
            int idx = i * 256 + tid;
            int row = idx >> 4, c16 = idx & 15;
            uint32_t off = (uint32_t)row * PADB + (uint32_t)c16 * 16;
            *reinterpret_cast<float4*>(sm + SM_WHI + off) = sh[idx];
            *reinterpret_cast<float4*>(sm + SM_WLO + off) = sl[idx];
        }
    }
    __syncthreads();

    do_gemm(smb, wm, wn, lane, acc);

    // ---- epilogue 2 ----
    const int r0 = wm * 32 + (lane >> 2);
    if (Wfc == nullptr) {
#pragma unroll
        for (int mt = 0; mt < 2; mt++) {
            int ra = m_base + r0 + mt * 16;
            int rb = ra + 8;
#pragma unroll
            for (int nt = 0; nt < 8; nt++) {
                int c = wn * 64 + nt * 8 + (lane & 3) * 2;
                float bc0 = __ldg(bb + c), bc1 = __ldg(bb + c + 1);
                float v0 = acc[mt][nt][0] + bc0;
                float v1 = acc[mt][nt][1] + bc1;
                float v2 = acc[mt][nt][2] + bc0;
                float v3 = acc[mt][nt][3] + bc1;
                if (final_relu) {
                    v0 = v0 > 0.f ? v0 : 0.f; v1 = v1 > 0.f ? v1 : 0.f;
                    v2 = v2 > 0.f ? v2 : 0.f; v3 = v3 > 0.f ? v3 : 0.f;
                }
                if (ra < NND) *reinterpret_cast<float2*>(out + (size_t)ra * 128 + c) = make_float2(v0, v1);
                if (rb < NND) *reinterpret_cast<float2*>(out + (size_t)rb * 128 + c) = make_float2(v2, v3);
            }
        }
    } else {
        float* fcb = reinterpret_cast<float*>(sm + SM_FC);
#pragma unroll
        for (int mt = 0; mt < 2; mt++) {
            float sa0 = 0.f, sa1 = 0.f, sb0 = 0.f, sb1 = 0.f;
#pragma unroll
            for (int nt = 0; nt < 8; nt++) {
                int c = wn * 64 + nt * 8 + (lane & 3) * 2;
                float bc0 = __ldg(bb + c), bc1 = __ldg(bb + c + 1);
                float w00 = __ldg(Wfc + c * 2),       w01 = __ldg(Wfc + c * 2 + 1);
                float w10 = __ldg(Wfc + (c + 1) * 2), w11 = __ldg(Wfc + (c + 1) * 2 + 1);
                float v0 = acc[mt][nt][0] + bc0;
                float v1 = acc[mt][nt][1] + bc1;
                float v2 = acc[mt][nt][2] + bc0;
                float v3 = acc[mt][nt][3] + bc1;
                sa0 += v0 * w00 + v1 * w10;
                sa1 += v0 * w01 + v1 * w11;
                sb0 += v2 * w00 + v3 * w10;
                sb1 += v2 * w01 + v3 * w11;
            }
#pragma unroll
            for (int o = 1; o < 4; o <<= 1) {
                sa0 += __shfl_xor_sync(0xffffffffu, sa0, o);
                sa1 += __shfl_xor_sync(0xffffffffu, sa1, o);
                sb0 += __shfl_xor_sync(0xffffffffu, sb0, o);
                sb1 += __shfl_xor_sync(0xffffffffu, sb1, o);
            }
            if ((lane & 3) == 0) {
                int r = r0 + mt * 16;
                fcb[(r * 2 + wn) * 2 + 0] = sa0;
                fcb[(r * 2 + wn) * 2 + 1] = sa1;
                fcb[((r + 8) * 2 + wn) * 2 + 0] = sb0;
                fcb[((r + 8) * 2 + wn) * 2 + 1] = sb1;
            }
        }
        __syncthreads();
        if (tid < 128) {
            int m = m_base + tid;
            if (m < NND) {
                out[(size_t)m * 2 + 0] = fcb[tid * 4 + 0] + fcb[tid * 4 + 2] + __ldg(bfc + 0);
                out[(size_t)m * 2 + 1] = fcb[tid * 4 + 1] + fcb[tid * 4 + 3] + __ldg(bfc + 1);
            }
        }
    }
}

// ---------------- launch ----------------
extern "C" void kernel_launch(void* const* d_in, const int* in_sizes, int n_in,
                              void* d_out, int out_size) {
    const float* x   = (const float*)d_in[0];
    const void*  ei  = d_in[1];
    const float* W1a = (const float*)d_in[2];
    const float* b1a = (const float*)d_in[3];
    const float* W1b = (const float*)d_in[4];
    const float* b1b = (const float*)d_in[5];
    const float* W2a = (const float*)d_in[6];
    const float* b2a = (const float*)d_in[7];
    const float* W2b = (const float*)d_in[8];
    const float* b2b = (const float*)d_in[9];
    const float* Wfc = (const float*)d_in[10];
    const float* bfc = (const float*)d_in[11];
    float* out = (float*)d_out;

    void *pA = nullptr, *pB = nullptr, *pW = nullptr;
    cudaGetSymbolAddress(&pA, g_bufA);
    cudaGetSymbolAddress(&pB, g_bufB);
    cudaGetSymbolAddress(&pW, g_wb);
    const __nv_bfloat16* wb = (const __nv_bfloat16*)pW;

    cudaFuncSetAttribute(k_mlp_mma, cudaFuncAttributeMaxDynamicSharedMemorySize, SM_TOTAL);

    const int GMLP = (NND + 127) / 128;   // 391
    const int GGAT = 592;                  // persistent work-stealing grid (4 blocks/SM)

    k_detect<<<1, 32>>>((const long long*)ei);
    k_zero_deg<<<(NND + 255) / 256, 256>>>();
    k_hist<<<NE / 256, 256>>>(ei);
    k_s1<<<NSB, SCB>>>();
    k_s2<<<1, 256>>>();
    k_s3<<<NSB, SCB>>>();
    k_fill<<<NE / 256, 256>>>(ei);
    k_prepw<<<4, 256>>>(W1a, W1b, W2a, W2b);

    // layer 1
    k_gather<<<GGAT, 256>>>((const float4*)x, (float4*)pA, 0);
    k_mlp_mma<<<GMLP, 256, SM_TOTAL>>>((const float*)pA,
        wb + 0 * 16384, wb + 1 * 16384, wb + 2 * 16384, wb + 3 * 16384,
        b1a, b1b, (float*)pB, 1, nullptr, nullptr);
    // layer 2 + FC head
    k_gather<<<GGAT, 256>>>((const float4*)pB, (float4*)pA, 1);
    k_mlp_mma<<<GMLP, 256, SM_TOTAL>>>((const float*)pA,
        wb + 4 * 16384, wb + 5 * 16384, wb + 6 * 16384, wb + 7 * 16384,
        b2a, b2b, out, 0, Wfc, bfc);
}

// round 13
// speedup vs baseline: 1.7357x; 1.7357x over previous
#include <cuda_runtime.h>
#include <cuda_bf16.h>
#include <cstdint>

#define NND 50000
#define NE  800000
#define HID 128

#define SCB 256
#define NSB ((NND + SCB - 1) / SCB)

#define PADB 272           // bytes per smem tile row (128 bf16 + 8 pad)
#define TILEB (128 * PADB)

#define SM_AHI 0
#define SM_ALO (SM_AHI + TILEB)
#define SM_WHI (SM_ALO + TILEB)
#define SM_WLO (SM_WHI + TILEB)
#define SM_FC  (SM_WLO + TILEB)
#define SM_TOTAL (SM_FC + 128 * 4 * 4)

// ---------------- device scratch ----------------
__device__ int   g_deg[NND];
__device__ int   g_rowptr[NND + 1];
__device__ int   g_cursor[NND];
__device__ int   g_col[NE];
__device__ int   g_part[NSB];
__device__ int   g_partoff[NSB];
__device__ float g_bufA[(size_t)NND * HID];
__device__ float g_bufB[(size_t)NND * HID];
__device__ __nv_bfloat16 g_wb[8][16384];  // {W1a,W1b,W2a,W2b} x {hi,lo}, [n][k]
__device__ int   g_is64;

// ---------------- PTX helpers ----------------
__device__ __forceinline__ uint32_t smem_u32(const void* p) {
    uint32_t a;
    asm("{ .reg .u64 t; cvta.to.shared.u64 t, %1; cvt.u32.u64 %0, t; }" : "=r"(a) : "l"(p));
    return a;
}
__device__ __forceinline__ void ldsm_x4(uint32_t* r, uint32_t addr) {
    asm volatile("ldmatrix.sync.aligned.m8n8.x4.shared.b16 {%0,%1,%2,%3}, [%4];"
                 : "=r"(r[0]), "=r"(r[1]), "=r"(r[2]), "=r"(r[3]) : "r"(addr));
}
__device__ __forceinline__ void ldsm_x2(uint32_t* r, uint32_t addr) {
    asm volatile("ldmatrix.sync.aligned.m8n8.x2.shared.b16 {%0,%1}, [%2];"
                 : "=r"(r[0]), "=r"(r[1]) : "r"(addr));
}
__device__ __forceinline__ void mma16816(float* c, const uint32_t* a, const uint32_t* b) {
    asm volatile("mma.sync.aligned.m16n8k16.row.col.f32.bf16.bf16.f32 "
                 "{%0,%1,%2,%3}, {%4,%5,%6,%7}, {%8,%9}, {%0,%1,%2,%3};"
                 : "+f"(c[0]), "+f"(c[1]), "+f"(c[2]), "+f"(c[3])
                 : "r"(a[0]), "r"(a[1]), "r"(a[2]), "r"(a[3]), "r"(b[0]), "r"(b[1]));
}
__device__ __forceinline__ uint32_t pack_bf16_hi(float v0, float v1, uint32_t& lop) {
    __nv_bfloat16 h0 = __float2bfloat16(v0);
    __nv_bfloat16 h1 = __float2bfloat16(v1);
    __nv_bfloat16 l0 = __float2bfloat16(v0 - __bfloat162float(h0));
    __nv_bfloat16 l1 = __float2bfloat16(v1 - __bfloat162float(h1));
    lop = ((uint32_t)__bfloat16_as_ushort(l1) << 16) | __bfloat16_as_ushort(l0);
    return ((uint32_t)__bfloat16_as_ushort(h1) << 16) | __bfloat16_as_ushort(h0);
}

// ---------------- zero degrees + edge dtype detection (merged) ----------------
__global__ void k_zero_deg(const long long* __restrict__ ei) {
    int i = blockIdx.x * blockDim.x + threadIdx.x;
    if (i < NND) g_deg[i] = 0;
    if (blockIdx.x == 0 && threadIdx.x < 32) {
        int lane = threadIdx.x;
        unsigned long long h = ((unsigned long long)ei[lane]) >> 32;
        h |= ((unsigned long long)ei[lane + 32]) >> 32;
        unsigned any = __ballot_sync(0xffffffffu, h != 0ull);
        if (lane == 0) g_is64 = (any == 0u) ? 1 : 0;
    }
}

// ---------------- histogram + weight prep (merged; prep = 4 trailing blocks) ----------------
#define HISTB (NE / 256)   // 3125
__global__ void k_hist(const void* __restrict__ ei,
                       const float* __restrict__ W0, const float* __restrict__ W1,
                       const float* __restrict__ W2, const float* __restrict__ W3) {
    if (blockIdx.x >= HISTB) {
        int mat = blockIdx.x - HISTB;
        const float* W = (mat == 0) ? W0 : (mat == 1) ? W1 : (mat == 2) ? W2 : W3;
        uint32_t* hiB = reinterpret_cast<uint32_t*>(g_wb[mat * 2]);
        uint32_t* loB = reinterpret_cast<uint32_t*>(g_wb[mat * 2 + 1]);
        for (int idx = threadIdx.x; idx < 8192; idx += blockDim.x) {
            int kp = idx & 63, n = idx >> 6, k = kp * 2;
            float a0 = W[k * 128 + n];
            float a1 = W[(k + 1) * 128 + n];
            uint32_t lp, hp = pack_bf16_hi(a0, a1, lp);
            hiB[n * 64 + kp] = hp;
            loB[n * 64 + kp] = lp;
        }
        return;
    }
    int e = blockIdx.x * blockDim.x + threadIdx.x;
    int d;
    if (g_is64) d = (int)reinterpret_cast<const long long*>(ei)[NE + e];
    else        d = reinterpret_cast<const int*>(ei)[NE + e];
    atomicAdd(&g_deg[d], 1);
}

// ---------------- scan (3 phases, proven) ----------------
__global__ void k_s1() {
    int b = blockIdx.x, t = threadIdx.x;
    int idx = b * SCB + t;
    int v = (idx < NND) ? g_deg[idx] : 0;
#pragma unroll
    for (int o = 16; o; o >>= 1) v += __shfl_down_sync(0xffffffffu, v, o);
    __shared__ int ws[8];
    if ((t & 31) == 0) ws[t >> 5] = v;
    __syncthreads();
    if (t == 0) {
        int s = 0;
#pragma unroll
        for (int i = 0; i < 8; i++) s += ws[i];
        g_part[b] = s;
    }
}
__global__ void k_s2() {
    int t = threadIdx.x, lane = t & 31, w = t >> 5;
    int v = (t < NSB) ? g_part[t] : 0;
    int iv = v;
#pragma unroll
    for (int o = 1; o < 32; o <<= 1) {
        int u = __shfl_up_sync(0xffffffffu, iv, o);
        if (lane >= o) iv += u;
    }
    __shared__ int ws[8], wso[8];
    if (lane == 31) ws[w] = iv;
    __syncthreads();
    if (t == 0) {
        int run = 0;
#pragma unroll
        for (int i = 0; i < 8; i++) { wso[i] = run; run += ws[i]; }
        g_rowptr[NND] = NE;
    }
    __syncthreads();
    if (t < NSB) g_partoff[t] = wso[w] + iv - v;
}
__global__ void k_s3() {
    int b = blockIdx.x, t = threadIdx.x, lane = t & 31, w = t >> 5;
    int idx = b * SCB + t;
    int v = (idx < NND) ? g_deg[idx] : 0;
    int iv = v;
#pragma unroll
    for (int o = 1; o < 32; o <<= 1) {
        int u = __shfl_up_sync(0xffffffffu, iv, o);
        if (lane >= o) iv += u;
    }
    __shared__ int ws[8], wso[8];
    if (lane == 31) ws[w] = iv;
    __syncthreads();
    if (t == 0) {
        int run = 0;
#pragma unroll
        for (int i = 0; i < 8; i++) { wso[i] = run; run += ws[i]; }
    }
    __syncthreads();
    int excl = g_partoff[b] + wso[w] + iv - v;
    if (idx < NND) { g_rowptr[idx] = excl; g_cursor[idx] = excl; }
}
__global__ void k_fill(const void* __restrict__ ei) {
    int e = blockIdx.x * blockDim.x + threadIdx.x;
    if (e >= NE) return;
    int s, d;
    if (g_is64) {
        s = (int)reinterpret_cast<const long long*>(ei)[e];
        d = (int)reinterpret_cast<const long long*>(ei)[NE + e];
    } else {
        s = reinterpret_cast<const int*>(ei)[e];
        d = reinterpret_cast<const int*>(ei)[NE + e];
    }
    int pos = atomicAdd(&g_cursor[d], 1);
    g_col[pos] = s;
}

// ---------------- static gather (warp per node, ILP x4) ----------------
__global__ void k_gather(const float4* __restrict__ in4, float4* __restrict__ out4) {
    int node = (int)((blockIdx.x * blockDim.x + threadIdx.x) >> 5);
    if (node >= NND) return;
    int lane = threadIdx.x & 31;
    float4 a0 = in4[(size_t)node * 32 + lane];
    float4 a1 = make_float4(0.f, 0.f, 0.f, 0.f);
    int beg = g_rowptr[node], end = g_rowptr[node + 1];
    int k = beg;
    for (; k + 4 <= end; k += 4) {
        int j0 = g_col[k], j1 = g_col[k + 1], j2 = g_col[k + 2], j3 = g_col[k + 3];
        float4 v0 = in4[(size_t)j0 * 32 + lane];
        float4 v1 = in4[(size_t)j1 * 32 + lane];
        float4 v2 = in4[(size_t)j2 * 32 + lane];
        float4 v3 = in4[(size_t)j3 * 32 + lane];
        a0.x += v0.x; a0.y += v0.y; a0.z += v0.z; a0.w += v0.w;
        a1.x += v1.x; a1.y += v1.y; a1.z += v1.z; a1.w += v1.w;
        a0.x += v2.x; a0.y += v2.y; a0.z += v2.z; a0.w += v2.w;
        a1.x += v3.x; a1.y += v3.y; a1.z += v3.z; a1.w += v3.w;
    }
    for (; k < end; k++) {
        int j = g_col[k];
        float4 v = in4[(size_t)j * 32 + lane];
        a0.x += v.x; a0.y += v.y; a0.z += v.z; a0.w += v.w;
    }
    a0.x += a1.x; a0.y += a1.y; a0.z += a1.z; a0.w += a1.w;
    out4[(size_t)node * 32 + lane] = a0;
}

// ---------------- GEMM core: 3-phase bf16 split, acc in fp32 ----------------
__device__ __forceinline__ void do_gemm(uint32_t smb, int wm, int wn, int lane,
                                        float acc[2][8][4]) {
#pragma unroll
    for (int mt = 0; mt < 2; mt++)
#pragma unroll
        for (int nt = 0; nt < 8; nt++)
#pragma unroll
            for (int i = 0; i < 4; i++) acc[mt][nt][i] = 0.f;

    const uint32_t a_bases[3] = { smb + SM_AHI, smb + SM_AHI, smb + SM_ALO };
    const uint32_t w_bases[3] = { smb + SM_WHI, smb + SM_WLO, smb + SM_WHI };

    const int a_row0 = wm * 32 + (lane & 15);
    const int a_cofs = (lane >> 4) * 8;
    const int b_row0 = wn * 64 + (lane & 7);
    const int b_cofs = ((lane >> 3) & 1) * 8;

#pragma unroll
    for (int p = 0; p < 3; p++) {
        const uint32_t Ab = a_bases[p];
        const uint32_t Wb = w_bases[p];
#pragma unroll
        for (int ks = 0; ks < 8; ks++) {
            const int k0 = ks * 16;
            uint32_t afrag[2][4];
#pragma unroll
            for (int mt = 0; mt < 2; mt++)
                ldsm_x4(afrag[mt], Ab + (uint32_t)(a_row0 + mt * 16) * PADB
                                      + (uint32_t)(k0 + a_cofs) * 2);
            uint32_t bfrag[8][2];
#pragma unroll
            for (int nt = 0; nt < 8; nt++)
                ldsm_x2(bfrag[nt], Wb + (uint32_t)(b_row0 + nt * 8) * PADB
                                      + (uint32_t)(k0 + b_cofs) * 2);
#pragma unroll
            for (int mt = 0; mt < 2; mt++)
#pragma unroll
                for (int nt = 0; nt < 8; nt++)
                    mma16816(acc[mt][nt], afrag[mt], bfrag[nt]);
        }
    }
}

// ---------------- MLP kernel: 2 GEMMs + epilogues ----------------
__global__ void __launch_bounds__(256, 1) k_mlp_mma(
    const float* __restrict__ A,
    const __nv_bfloat16* __restrict__ WaHi, const __nv_bfloat16* __restrict__ WaLo,
    const __nv_bfloat16* __restrict__ WbHi, const __nv_bfloat16* __restrict__ WbLo,
    const float* __restrict__ ba, const float* __restrict__ bb,
    float* __restrict__ out, int final_relu,
    const float* __restrict__ Wfc, const float* __restrict__ bfc) {
    extern __shared__ char sm[];
    const uint32_t smb = smem_u32(sm);
    const int tid = threadIdx.x;
    const int wid = tid >> 5;
    const int lane = tid & 31;
    const int wm = wid & 3;
    const int wn = wid >> 2;
    const int m_base = blockIdx.x * 128;

    // ---- load A tile: fp32 -> bf16 hi/lo ----
    {
#pragma unroll
        for (int it = 0; it < 16; it++) {
            int r = wid * 16 + it;
            int m = m_base + r;
            float4 v = make_float4(0.f, 0.f, 0.f, 0.f);
            if (m < NND) v = *reinterpret_cast<const float4*>(A + (size_t)m * 128 + lane * 4);
            uint32_t l0, l1;
            uint32_t h0 = pack_bf16_hi(v.x, v.y, l0);
            uint32_t h1 = pack_bf16_hi(v.z, v.w, l1);
            uint32_t off = (uint32_t)r * PADB + (uint32_t)lane * 8;
            *reinterpret_cast<uint2*>(sm + SM_AHI + off) = make_uint2(h0, h1);
            *reinterpret_cast<uint2*>(sm + SM_ALO + off) = make_uint2(l0, l1);
        }
    }
    // ---- copy Wa blobs ----
    {
        const float4* sh = reinterpret_cast<const float4*>(WaHi);
        const float4* sl = reinterpret_cast<const float4*>(WaLo);
#pragma unroll
        for (int i = 0; i < 8; i++) {
            int idx = i * 256 + tid;
            int row = idx >> 4, c16 = idx & 15;
            uint32_t off = (uint32_t)row * PADB + (uint32_t)c16 * 16;
            *reinterpret_cast<float4*>(sm + SM_WHI + off) = sh[idx];
            *reinterpret_cast<float4*>(sm + SM_WLO + off) = sl[idx];
        }
    }
    __syncthreads();

    float acc[2][8][4];
    do_gemm(smb, wm, wn, lane, acc);
    __syncthreads();

    // ---- epilogue 1: bias + relu -> back into A tile ----
    {
        const int r0 = wm * 32 + (lane >> 2);
#pragma unroll
        for (int mt = 0; mt < 2; mt++) {
#pragma unroll
            for (int nt = 0; nt < 8; nt++) {
                int c = wn * 64 + nt * 8 + (lane & 3) * 2;
                float bc0 = __ldg(ba + c), bc1 = __ldg(ba + c + 1);
                float v0 = acc[mt][nt][0] + bc0;
                float v1 = acc[mt][nt][1] + bc1;
                float v2 = acc[mt][nt][2] + bc0;
                float v3 = acc[mt][nt][3] + bc1;
                v0 = v0 > 0.f ? v0 : 0.f; v1 = v1 > 0.f ? v1 : 0.f;
                v2 = v2 > 0.f ? v2 : 0.f; v3 = v3 > 0.f ? v3 : 0.f;
                int r = r0 + mt * 16;
                uint32_t lo;
                uint32_t hi = pack_bf16_hi(v0, v1, lo);
                uint32_t off = (uint32_t)r * PADB + (uint32_t)c * 2;
                *reinterpret_cast<uint32_t*>(sm + SM_AHI + off) = hi;
                *reinterpret_cast<uint32_t*>(sm + SM_ALO + off) = lo;
                hi = pack_bf16_hi(v2, v3, lo);
                off = (uint32_t)(r + 8) * PADB + (uint32_t)c * 2;
                *reinterpret_cast<uint32_t*>(sm + SM_AHI + off) = hi;
                *reinterpret_cast<uint32_t*>(sm + SM_ALO + off) = lo;
            }
        }
    }
    // ---- copy Wb blobs ----
    {
        const float4* sh = reinterpret_cast<const float4*>(WbHi);
        const float4* sl = reinterpret_cast<const float4*>(WbLo);
#pragma unroll
        for (int i = 0; i < 8; i++) {
            int idx = i * 256 + tid;
            int row = idx >> 4, c16 = idx & 15;
            uint32_t off = (uint32_t)row * PADB + (uint32_t)c16 * 16;
            *reinterpret_cast<float4*>(sm + SM_WHI + off) = sh[idx];
            *reinterpret_cast<float4*>(sm + SM_WLO + off) = sl[idx];
        }
    }
    __syncthreads();

    do_gemm(smb, wm, wn, lane, acc);

    // ---- epilogue 2 ----
    const int r0 = wm * 32 + (lane >> 2);
    if (Wfc == nullptr) {
#pragma unroll
        for (int mt = 0; mt < 2; mt++) {
            int ra = m_base + r0 + mt * 16;
            int rb = ra + 8;
#pragma unroll
            for (int nt = 0; nt < 8; nt++) {
                int c = wn * 64 + nt * 8 + (lane & 3) * 2;
                float bc0 = __ldg(bb + c), bc1 = __ldg(bb + c + 1);
                float v0 = acc[mt][nt][0] + bc0;
                float v1 = acc[mt][nt][1] + bc1;
                float v2 = acc[mt][nt][2] + bc0;
                float v3 = acc[mt][nt][3] + bc1;
                if (final_relu) {
                    v0 = v0 > 0.f ? v0 : 0.f; v1 = v1 > 0.f ? v1 : 0.f;
                    v2 = v2 > 0.f ? v2 : 0.f; v3 = v3 > 0.f ? v3 : 0.f;
                }
                if (ra < NND) *reinterpret_cast<float2*>(out + (size_t)ra * 128 + c) = make_float2(v0, v1);
                if (rb < NND) *reinterpret_cast<float2*>(out + (size_t)rb * 128 + c) = make_float2(v2, v3);
            }
        }
    } else {
        float* fcb = reinterpret_cast<float*>(sm + SM_FC);
#pragma unroll
        for (int mt = 0; mt < 2; mt++) {
            float sa0 = 0.f, sa1 = 0.f, sb0 = 0.f, sb1 = 0.f;
#pragma unroll
            for (int nt = 0; nt < 8; nt++) {
                int c = wn * 64 + nt * 8 + (lane & 3) * 2;
                float bc0 = __ldg(bb + c), bc1 = __ldg(bb + c + 1);
                float w00 = __ldg(Wfc + c * 2),       w01 = __ldg(Wfc + c * 2 + 1);
                float w10 = __ldg(Wfc + (c + 1) * 2), w11 = __ldg(Wfc + (c + 1) * 2 + 1);
                float v0 = acc[mt][nt][0] + bc0;
                float v1 = acc[mt][nt][1] + bc1;
                float v2 = acc[mt][nt][2] + bc0;
                float v3 = acc[mt][nt][3] + bc1;
                sa0 += v0 * w00 + v1 * w10;
                sa1 += v0 * w01 + v1 * w11;
                sb0 += v2 * w00 + v3 * w10;
                sb1 += v2 * w01 + v3 * w11;
            }
#pragma unroll
            for (int o = 1; o < 4; o <<= 1) {
                sa0 += __shfl_xor_sync(0xffffffffu, sa0, o);
                sa1 += __shfl_xor_sync(0xffffffffu, sa1, o);
                sb0 += __shfl_xor_sync(0xffffffffu, sb0, o);
                sb1 += __shfl_xor_sync(0xffffffffu, sb1, o);
            }
            if ((lane & 3) == 0) {
                int r = r0 + mt * 16;
                fcb[(r * 2 + wn) * 2 + 0] = sa0;
                fcb[(r * 2 + wn) * 2 + 1] = sa1;
                fcb[((r + 8) * 2 + wn) * 2 + 0] = sb0;
                fcb[((r + 8) * 2 + wn) * 2 + 1] = sb1;
            }
        }
        __syncthreads();
        if (tid < 128) {
            int m = m_base + tid;
            if (m < NND) {
                out[(size_t)m * 2 + 0] = fcb[tid * 4 + 0] + fcb[tid * 4 + 2] + __ldg(bfc + 0);
                out[(size_t)m * 2 + 1] = fcb[tid * 4 + 1] + fcb[tid * 4 + 3] + __ldg(bfc + 1);
            }
        }
    }
}

// ---------------- launch ----------------
extern "C" void kernel_launch(void* const* d_in, const int* in_sizes, int n_in,
                              void* d_out, int out_size) {
    const float* x   = (const float*)d_in[0];
    const void*  ei  = d_in[1];
    const float* W1a = (const float*)d_in[2];
    const float* b1a = (const float*)d_in[3];
    const float* W1b = (const float*)d_in[4];
    const float* b1b = (const float*)d_in[5];
    const float* W2a = (const float*)d_in[6];
    const float* b2a = (const float*)d_in[7];
    const float* W2b = (const float*)d_in[8];
    const float* b2b = (const float*)d_in[9];
    const float* Wfc = (const float*)d_in[10];
    const float* bfc = (const float*)d_in[11];
    float* out = (float*)d_out;

    void *pA = nullptr, *pB = nullptr, *pW = nullptr;
    cudaGetSymbolAddress(&pA, g_bufA);
    cudaGetSymbolAddress(&pB, g_bufB);
    cudaGetSymbolAddress(&pW, g_wb);
    const __nv_bfloat16* wb = (const __nv_bfloat16*)pW;

    cudaFuncSetAttribute(k_mlp_mma, cudaFuncAttributeMaxDynamicSharedMemorySize, SM_TOTAL);

    const int GMLP = (NND + 127) / 128;   // 391
    const int GW   = (NND + 7) / 8;       // static warp-per-node gather

    k_zero_deg<<<(NND + 255) / 256, 256>>>((const long long*)ei);
    k_hist<<<HISTB + 4, 256>>>(ei, W1a, W1b, W2a, W2b);
    k_s1<<<NSB, SCB>>>();
    k_s2<<<1, 256>>>();
    k_s3<<<NSB, SCB>>>();
    k_fill<<<NE / 256, 256>>>(ei);

    // layer 1
    k_gather<<<GW, 256>>>((const float4*)x, (float4*)pA);
    k_mlp_mma<<<GMLP, 256, SM_TOTAL>>>((const float*)pA,
        wb + 0 * 16384, wb + 1 * 16384, wb + 2 * 16384, wb + 3 * 16384,
        b1a, b1b, (float*)pB, 1, nullptr, nullptr);
    // layer 2 + FC head
    k_gather<<<GW, 256>>>((const float4*)pB, (float4*)pA);
    k_mlp_mma<<<GMLP, 256, SM_TOTAL>>>((const float*)pA,
        wb + 4 * 16384, wb + 5 * 16384, wb + 6 * 16384, wb + 7 * 16384,
        b2a, b2b, out, 0, Wfc, bfc);
}